// round 3
// baseline (speedup 1.0000x reference)
#include <cuda_runtime.h>
#include <cuda_bf16.h>
#include <cstdint>

#define TT   4096   // sequence length T
#define EE   256    // embedding dim
#define HH   256    // hidden
#define LL   18     // labels
#define NG   1024   // 4*H gate rows
#define CS   8      // cluster size (CTAs per direction)
#define UPC  32     // hidden units per CTA
#define NEGV -10000.0f
#define STARTL 16
#define STOPL  17
#define TPB  32     // timesteps per pre_gemm block

typedef unsigned long long ull;

// ---------------- scratch (static device globals; no runtime alloc) --------
__device__ float g_pre[2][(size_t)TT * NG];   // precomputed x@w_ih.T + b
__device__ float g_hs[2][(size_t)TT * HH];    // hidden states (fwd, bwd)
__device__ float g_emit[(size_t)TT * LL];

// ---------------- helpers --------------------------------------------------
__device__ __forceinline__ float sigf(float x) {
    return 1.0f / (1.0f + __expf(-x));
}
__device__ __forceinline__ float tanhf_fast(float x) {
    return 1.0f - 2.0f / (__expf(2.0f * x) + 1.0f);
}
__device__ __forceinline__ uint32_t smem_u32(const void* p) {
    uint32_t a;
    asm("{ .reg .u64 t; cvta.to.shared.u64 t, %1; cvt.u32.u64 %0, t; }"
        : "=r"(a) : "l"(p));
    return a;
}
__device__ __forceinline__ uint32_t mapa_rank(uint32_t laddr, uint32_t rank) {
    uint32_t r;
    asm("mapa.shared::cluster.u32 %0, %1, %2;" : "=r"(r) : "r"(laddr), "r"(rank));
    return r;
}
__device__ __forceinline__ void bulk_copy_c2c(uint32_t dst_remote, uint32_t src_local,
                                              uint32_t bytes, uint32_t rmbar) {
    asm volatile(
        "cp.async.bulk.shared::cluster.shared::cta.mbarrier::complete_tx::bytes "
        "[%0], [%1], %2, [%3];"
        :: "r"(dst_remote), "r"(src_local), "r"(bytes), "r"(rmbar) : "memory");
}
__device__ __forceinline__ void fence_proxy_async_cta() {
    asm volatile("fence.proxy.async.shared::cta;" ::: "memory");
}
__device__ __forceinline__ void mbar_init(uint32_t addr, uint32_t cnt) {
    asm volatile("mbarrier.init.shared.b64 [%0], %1;" :: "r"(addr), "r"(cnt) : "memory");
}
__device__ __forceinline__ void mbar_expect_tx(uint32_t addr, uint32_t bytes) {
    asm volatile("mbarrier.arrive.expect_tx.shared.b64 _, [%0], %1;"
                 :: "r"(addr), "r"(bytes) : "memory");
}
__device__ __forceinline__ void mbar_wait(uint32_t addr, uint32_t parity) {
    uint32_t done;
    asm volatile(
        "{\n\t.reg .pred p;\n\t"
        "mbarrier.try_wait.parity.acquire.cta.shared::cta.b64 p, [%1], %2;\n\t"
        "selp.b32 %0, 1, 0, p;\n\t}"
        : "=r"(done) : "r"(addr), "r"(parity) : "memory");
    while (!done) {
        asm volatile(
            "{\n\t.reg .pred p;\n\t"
            "mbarrier.try_wait.parity.acquire.cta.shared::cta.b64 p, [%1], %2, 0x989680;\n\t"
            "selp.b32 %0, 1, 0, p;\n\t}"
            : "=r"(done) : "r"(addr), "r"(parity) : "memory");
    }
}
__device__ __forceinline__ ull pack2(float x, float y) {
    ull d;
    asm("mov.b64 %0, {%1, %2};" : "=l"(d) : "f"(x), "f"(y));
    return d;
}
__device__ __forceinline__ void unpack2(float& lo, float& hi, ull a) {
    asm("mov.b64 {%0, %1}, %2;" : "=f"(lo), "=f"(hi) : "l"(a));
}
__device__ __forceinline__ void fma2(ull& d, ull a, ull b) {
    asm("fma.rn.f32x2 %0, %1, %2, %0;" : "+l"(d) : "l"(a), "l"(b));
}
__device__ __forceinline__ ull add2(ull a, ull b) {
    ull d;
    asm("add.rn.f32x2 %0, %1, %2;" : "=l"(d) : "l"(a), "l"(b));
    return d;
}

// ---------------- pre-GEMM: pre[d][t][row] = emb[feat[t]] . w_ih[row] + b --
// 32 timesteps per block -> weight re-stream cut 4x vs 8 t/block.
__global__ void __launch_bounds__(256) pre_gemm_kernel(
    const int* __restrict__ feats, const float* __restrict__ emb,
    const float* __restrict__ w_f, const float* __restrict__ b_f,
    const float* __restrict__ w_b, const float* __restrict__ b_b)
{
    __shared__ float xs[TPB][EE];
    const int tid = threadIdx.x;
    const int dir = blockIdx.y;
    const int t0  = blockIdx.x * TPB;
    const float* w  = dir ? w_b : w_f;
    const float* bb = dir ? b_b : b_f;
    float* pre = g_pre[dir];

    {   // gather TPB embedding rows into shared (8 threads per row)
        int i = tid >> 3, c = tid & 7;
        int f = feats[t0 + i];
        const float4* src = (const float4*)(emb + (size_t)f * EE);
        #pragma unroll
        for (int cc = 0; cc < 8; ++cc)
            ((float4*)xs[i])[c + cc * 8] = __ldg(src + c + cc * 8);
    }
    __syncthreads();

    for (int q = 0; q < 4; ++q) {
        const int row = q * 256 + tid;
        const float4* wp = (const float4*)(w + (size_t)row * EE);
        const float bv = __ldg(&bb[row]);
        float acc[TPB];
        #pragma unroll
        for (int i = 0; i < TPB; ++i) acc[i] = bv;
        for (int k4 = 0; k4 < 64; ++k4) {
            float4 wv = __ldg(wp + k4);
            #pragma unroll
            for (int i = 0; i < TPB; ++i) {
                float4 xv = *(const float4*)&xs[i][k4 * 4];
                acc[i] = fmaf(wv.x, xv.x, acc[i]);
                acc[i] = fmaf(wv.y, xv.y, acc[i]);
                acc[i] = fmaf(wv.z, xv.z, acc[i]);
                acc[i] = fmaf(wv.w, xv.w, acc[i]);
            }
        }
        #pragma unroll
        for (int i = 0; i < TPB; ++i)
            pre[(size_t)(t0 + i) * NG + row] = acc[i];
    }
}

// ---------------- persistent LSTM: 2 clusters of 8 CTAs ---------------------
// CTA owns 32 hidden units => 128 gate rows; 2 threads/row (256 threads).
// lane = unit_local*8 + gate*2 + half (all 4 gates of a unit in one warp).
// h published as ONE 128B cp.async.bulk per peer CTA (not 256 x 4B st.async).
__global__ void __cluster_dims__(CS, 1, 1) __launch_bounds__(256, 1)
lstm_kernel(const float* __restrict__ whh_f, const float* __restrict__ whh_b)
{
    __shared__ __align__(16) float sh_h[2][HH];      // assembled h (by step parity)
    __shared__ __align__(16) float sh_stage[2][UPC]; // local staging for publish
    __shared__ ull smbar[2];

    const int tid = threadIdx.x;
    const int dir = blockIdx.x / CS;
    uint32_t rank;
    asm("mov.u32 %0, %%cluster_ctarank;" : "=r"(rank));

    const int w = tid >> 5, l = tid & 31;
    const int unit  = w * 4 + (l >> 3);            // 0..31 within CTA
    const int gate  = (l >> 1) & 3;                // 0..3 (i,f,g,o)
    const int half  = l & 1;                       // which 128-chunk of h
    const int unit_global = (int)rank * UPC + unit;   // 0..255
    const int row_global  = gate * HH + unit_global;  // 0..1023
    const bool is_gl = ((l & 7) == 0);             // publisher lane per unit

    // pack recurrent weights into f32x2 registers (128 floats / thread)
    const float* wrow = (dir ? whh_b : whh_f) + (size_t)row_global * HH + half * 128;
    ulonglong2 w2[32];
    #pragma unroll
    for (int v = 0; v < 32; ++v) {
        float4 f = __ldg((const float4*)wrow + v);
        w2[v].x = pack2(f.x, f.y);
        w2[v].y = pack2(f.z, f.w);
    }

    const uint32_t loc_dst[2] = { smem_u32(&sh_h[0][(int)rank * UPC]),
                                  smem_u32(&sh_h[1][(int)rank * UPC]) };
    const uint32_t loc_stage[2] = { smem_u32(&sh_stage[0][0]),
                                    smem_u32(&sh_stage[1][0]) };
    const uint32_t loc_b[2] = { smem_u32(&smbar[0]), smem_u32(&smbar[1]) };
    // each of 8 lanes (of warp 0) owns one destination rank
    uint32_t rem_dst[2], rem_b[2];
    {
        const uint32_t r = (uint32_t)(l & 7);
        rem_dst[0] = mapa_rank(loc_dst[0], r);
        rem_dst[1] = mapa_rank(loc_dst[1], r);
        rem_b[0]   = mapa_rank(loc_b[0], r);
        rem_b[1]   = mapa_rank(loc_b[1], r);
    }

    for (int i = tid; i < 2 * HH; i += 256) ((float*)sh_h)[i] = 0.f;
    if (tid == 0) { mbar_init(loc_b[0], 1); mbar_init(loc_b[1], 1); }
    __syncthreads();
    asm volatile("barrier.cluster.arrive.aligned;" ::: "memory");
    asm volatile("barrier.cluster.wait.aligned;" ::: "memory");

    const float* pre = g_pre[dir];
    float* hs = g_hs[dir];
    float c = 0.f;

    // prefetch pre with distance 2 (covers DRAM latency ~577cy)
    auto tmap = [&](int n) { return dir ? (TT - 1 - n) : n; };
    float pre0 = 0.f, pre1 = 0.f;
    if (half == 0) {
        pre0 = __ldcg(&pre[(size_t)tmap(0) * NG + row_global]);
        pre1 = __ldcg(&pre[(size_t)tmap(1) * NG + row_global]);
    }

    for (int n = 0; n < TT; ++n) {
        const int tstep = tmap(n);
        if (n > 0) mbar_wait(loc_b[(n - 1) & 1], ((n - 1) >> 1) & 1);
        if (tid == 0) mbar_expect_tx(loc_b[n & 1], CS * UPC * 4);

        float pre2 = 0.f;
        if (half == 0 && n + 2 < TT)
            pre2 = __ldcg(&pre[(size_t)tmap(n + 2) * NG + row_global]);

        // ---- matvec slice: dot(w_row[half*128 .. +128), h_prev) -----------
        const ulonglong2* hp = (const ulonglong2*)&sh_h[(n + 1) & 1][half * 128];
        ull a0 = 0ull, a1 = 0ull, a2 = 0ull, a3 = 0ull;
        #pragma unroll
        for (int v = 0; v < 32; v += 2) {
            ulonglong2 h0 = hp[v], h1 = hp[v + 1];
            fma2(a0, w2[v].x, h0.x);     fma2(a1, w2[v].y, h0.y);
            fma2(a2, w2[v + 1].x, h1.x); fma2(a3, w2[v + 1].y, h1.y);
        }
        a0 = add2(add2(a0, a2), add2(a1, a3));
        float lo, hi; unpack2(lo, hi, a0);
        float dot = lo + hi;
        dot += __shfl_xor_sync(0xffffffffu, dot, 1);
        float val = dot + pre0;               // valid on even (half==0) lanes
        pre0 = pre1; pre1 = pre2;

        // ---- gather the 4 gates of this unit (all intra-warp) -------------
        const int base = l & 24;              // lane of (unit, gate0, half0)
        float gi = __shfl_sync(0xffffffffu, val, base);
        float gf = __shfl_sync(0xffffffffu, val, base + 2);
        float gg = __shfl_sync(0xffffffffu, val, base + 4);
        float go = __shfl_sync(0xffffffffu, val, base + 6);
        float iv = sigf(gi), fv = sigf(gf), ov = sigf(go);
        c = fv * c + iv * tanhf_fast(gg);     // replicated across unit lanes
        float h = ov * tanhf_fast(c);

        const int s = n & 1;
        if (is_gl) {
            sh_stage[s][unit] = h;                            // STS (local)
            hs[(size_t)tstep * HH + unit_global] = h;         // for emit
        }
        __syncthreads();                      // drains STS into smem
        if (w == 0 && l < CS) {               // 8 lanes, one peer each
            fence_proxy_async_cta();
            bulk_copy_c2c(rem_dst[s], loc_stage[s], UPC * 4, rem_b[s]);
        }
    }

    // drain final publish, then cluster-exit barrier (peer copies in flight)
    mbar_wait(loc_b[(TT - 1) & 1], ((TT - 1) >> 1) & 1);
    asm volatile("barrier.cluster.arrive.aligned;" ::: "memory");
    asm volatile("barrier.cluster.wait.aligned;" ::: "memory");
}

// ---------------- emit: [hf|hb] @ W_out.T + b_out --------------------------
__global__ void __launch_bounds__(128) emit_kernel(
    const float* __restrict__ Wo, const float* __restrict__ bo)
{
    const int idx = blockIdx.x * blockDim.x + threadIdx.x;
    if (idx >= TT * LL) return;
    const int t = idx / LL;
    const int l = idx - t * LL;
    const float4* hf = (const float4*)&g_hs[0][(size_t)t * HH];
    const float4* hb = (const float4*)&g_hs[1][(size_t)t * HH];
    const float4* wf = (const float4*)&Wo[(size_t)l * 2 * HH];
    const float4* wb = wf + 64;
    float acc = __ldg(&bo[l]);
    #pragma unroll 8
    for (int k = 0; k < 64; ++k) {
        float4 h4 = __ldg(hf + k), w4 = __ldg(wf + k);
        acc = fmaf(h4.x, w4.x, acc); acc = fmaf(h4.y, w4.y, acc);
        acc = fmaf(h4.z, w4.z, acc); acc = fmaf(h4.w, w4.w, acc);
        float4 h5 = __ldg(hb + k), w5 = __ldg(wb + k);
        acc = fmaf(h5.x, w5.x, acc); acc = fmaf(h5.y, w5.y, acc);
        acc = fmaf(h5.z, w5.z, acc); acc = fmaf(h5.w, w5.w, acc);
    }
    g_emit[idx] = acc;
}

// ---------------- viterbi + backtrack (single warp, bp in shared) ----------
// per-step max via fmax TREE (dep ~20cy) + equality mask + ffs for first-max
// argmax (same tie rule as jnp.argmax), instead of an 18-deep compare chain.
extern __shared__ unsigned char vit_sh[];
__global__ void viterbi_kernel(const float* __restrict__ trans,
                               float* __restrict__ out, int out_size)
{
    unsigned char* bp = vit_sh;                         // TT*LL bytes
    float* fvs = (float*)(vit_sh + (size_t)TT * LL);    // 2 x 32 floats

    const int l = threadIdx.x;
    float tr[LL];
    float tr_stop = 0.f;
    if (l < LL) {
        #pragma unroll
        for (int i = 0; i < LL; ++i) tr[i] = __ldg(&trans[i * LL + l]);
        tr_stop = __ldg(&trans[l * LL + STOPL]);
        fvs[l] = (l == STARTL) ? 0.f : NEGV;
    }
    __syncwarp();

    float e_nxt = (l < LL) ? __ldcg(&g_emit[l]) : 0.f;
    int cur = 0;
    for (int t = 0; t < TT; ++t) {
        const float e = e_nxt;
        if (l < LL && t + 1 < TT) e_nxt = __ldcg(&g_emit[(t + 1) * LL + l]);
        if (l < LL) {
            float sc[LL];
            #pragma unroll
            for (int i = 0; i < LL; ++i) sc[i] = fvs[cur * 32 + i] + tr[i];
            // tree max (depth 5)
            float m01 = fmaxf(sc[0], sc[1]),   m23 = fmaxf(sc[2], sc[3]);
            float m45 = fmaxf(sc[4], sc[5]),   m67 = fmaxf(sc[6], sc[7]);
            float m89 = fmaxf(sc[8], sc[9]),   mab = fmaxf(sc[10], sc[11]);
            float mcd = fmaxf(sc[12], sc[13]), mef = fmaxf(sc[14], sc[15]);
            float mgh = fmaxf(sc[16], sc[17]);
            float a = fmaxf(fmaxf(m01, m23), fmaxf(m45, m67));
            float b = fmaxf(fmaxf(m89, mab), fmaxf(mcd, mef));
            float m = fmaxf(fmaxf(a, b), mgh);
            unsigned mask = 0;
            #pragma unroll
            for (int i = 0; i < LL; ++i) mask |= (sc[i] == m) ? (1u << i) : 0u;
            int am = __ffs(mask) - 1;          // first index achieving max
            fvs[(cur ^ 1) * 32 + l] = m + e;
            bp[t * LL + l] = (unsigned char)am;
        }
        cur ^= 1;
        __syncwarp();
    }
    if (l < LL) fvs[cur * 32 + l] += tr_stop;   // terminal scores
    __syncwarp();

    if (l == 0) {
        float best = -3.4e38f; int bi = 0;
        #pragma unroll
        for (int i = 0; i < LL; ++i) {
            float v = fvs[cur * 32 + i];
            if (v > best) { best = v; bi = i; }
        }
        const int off = (out_size > TT) ? 1 : 0;
        if (off) out[0] = best;
        int tag = bi;
        for (int t = TT - 1; t >= 0; --t) {
            out[off + t] = (float)tag;
            if (t > 0) tag = (int)bp[t * LL + tag];
        }
    }
}

// ---------------- launch ----------------------------------------------------
extern "C" void kernel_launch(void* const* d_in, const int* in_sizes, int n_in,
                              void* d_out, int out_size)
{
    const int*   feats  = (const int*)d_in[0];
    const float* emb    = (const float*)d_in[1];
    const float* w_ih_f = (const float*)d_in[2];
    const float* w_hh_f = (const float*)d_in[3];
    const float* b_f    = (const float*)d_in[4];
    const float* w_ih_b = (const float*)d_in[5];
    const float* w_hh_b = (const float*)d_in[6];
    const float* b_b    = (const float*)d_in[7];
    const float* W_out  = (const float*)d_in[8];
    const float* b_out  = (const float*)d_in[9];
    const float* trans  = (const float*)d_in[10];
    float* out = (float*)d_out;

    const int vit_smem = TT * LL + 2 * 32 * (int)sizeof(float);  // ~74KB
    cudaFuncSetAttribute(viterbi_kernel,
                         cudaFuncAttributeMaxDynamicSharedMemorySize, vit_smem);

    pre_gemm_kernel<<<dim3(TT / TPB, 2), 256>>>(feats, emb, w_ih_f, b_f, w_ih_b, b_b);
    lstm_kernel<<<2 * CS, 256>>>(w_hh_f, w_hh_b);
    emit_kernel<<<(TT * LL + 127) / 128, 128>>>(W_out, b_out);
    viterbi_kernel<<<1, 32, vit_smem>>>(trans, out, out_size);
}

// round 4
// speedup vs baseline: 1.2894x; 1.2894x over previous
#include <cuda_runtime.h>
#include <cuda_bf16.h>
#include <cstdint>

#define TT   4096   // sequence length T
#define EE   256    // embedding dim
#define HH   256    // hidden
#define LL   18     // labels
#define NG   1024   // 4*H gate rows
#define CS   8      // cluster size (CTAs per direction)
#define UPC  32     // hidden units per CTA
#define NEGV -10000.0f
#define STARTL 16
#define STOPL  17
#define TPB  32     // timesteps per pre_gemm block

typedef unsigned long long ull;

// ---------------- scratch (static device globals; no runtime alloc) --------
__device__ float g_pre[2][(size_t)TT * NG];   // precomputed x@w_ih.T + b
__device__ float g_hs[2][(size_t)TT * HH];    // hidden states (fwd, bwd)
__device__ float g_emit[(size_t)TT * LL];

// ---------------- helpers --------------------------------------------------
__device__ __forceinline__ float rcpf(float x) {           // MUFU.RCP (approx)
    float y;
    asm("rcp.approx.f32 %0, %1;" : "=f"(y) : "f"(x));
    return y;
}
__device__ __forceinline__ float sigf(float x) {           // no precise div!
    return rcpf(1.0f + __expf(-x));
}
__device__ __forceinline__ float tanhf_fast(float x) {     // no precise div!
    return fmaf(-2.0f, rcpf(__expf(2.0f * x) + 1.0f), 1.0f);
}
__device__ __forceinline__ uint32_t smem_u32(const void* p) {
    uint32_t a;
    asm("{ .reg .u64 t; cvta.to.shared.u64 t, %1; cvt.u32.u64 %0, t; }"
        : "=r"(a) : "l"(p));
    return a;
}
__device__ __forceinline__ uint32_t mapa_rank(uint32_t laddr, uint32_t rank) {
    uint32_t r;
    asm("mapa.shared::cluster.u32 %0, %1, %2;" : "=r"(r) : "r"(laddr), "r"(rank));
    return r;
}
__device__ __forceinline__ void st_async_b32(uint32_t raddr, uint32_t v, uint32_t rmbar) {
    asm volatile(
        "st.async.shared::cluster.mbarrier::complete_tx::bytes.b32 [%0], %1, [%2];"
        :: "r"(raddr), "r"(v), "r"(rmbar) : "memory");
}
__device__ __forceinline__ void mbar_init(uint32_t addr, uint32_t cnt) {
    asm volatile("mbarrier.init.shared.b64 [%0], %1;" :: "r"(addr), "r"(cnt) : "memory");
}
__device__ __forceinline__ void mbar_expect_tx(uint32_t addr, uint32_t bytes) {
    asm volatile("mbarrier.arrive.expect_tx.shared.b64 _, [%0], %1;"
                 :: "r"(addr), "r"(bytes) : "memory");
}
__device__ __forceinline__ void mbar_wait(uint32_t addr, uint32_t parity) {
    uint32_t done;
    asm volatile(
        "{\n\t.reg .pred p;\n\t"
        "mbarrier.try_wait.parity.acquire.cluster.shared::cta.b64 p, [%1], %2;\n\t"
        "selp.b32 %0, 1, 0, p;\n\t}"
        : "=r"(done) : "r"(addr), "r"(parity) : "memory");
    while (!done) {
        asm volatile(
            "{\n\t.reg .pred p;\n\t"
            "mbarrier.try_wait.parity.acquire.cluster.shared::cta.b64 p, [%1], %2, 0x989680;\n\t"
            "selp.b32 %0, 1, 0, p;\n\t}"
            : "=r"(done) : "r"(addr), "r"(parity) : "memory");
    }
}
__device__ __forceinline__ ull pack2(float x, float y) {
    ull d;
    asm("mov.b64 %0, {%1, %2};" : "=l"(d) : "f"(x), "f"(y));
    return d;
}
__device__ __forceinline__ void unpack2(float& lo, float& hi, ull a) {
    asm("mov.b64 {%0, %1}, %2;" : "=f"(lo), "=f"(hi) : "l"(a));
}
__device__ __forceinline__ void fma2(ull& d, ull a, ull b) {
    asm("fma.rn.f32x2 %0, %1, %2, %0;" : "+l"(d) : "l"(a), "l"(b));
}
__device__ __forceinline__ ull add2(ull a, ull b) {
    ull d;
    asm("add.rn.f32x2 %0, %1, %2;" : "=l"(d) : "l"(a), "l"(b));
    return d;
}

// ---------------- pre-GEMM: pre[d][t][row] = emb[feat[t]] . w_ih[row] + b --
__global__ void __launch_bounds__(256) pre_gemm_kernel(
    const int* __restrict__ feats, const float* __restrict__ emb,
    const float* __restrict__ w_f, const float* __restrict__ b_f,
    const float* __restrict__ w_b, const float* __restrict__ b_b)
{
    __shared__ float xs[TPB][EE];
    const int tid = threadIdx.x;
    const int dir = blockIdx.y;
    const int t0  = blockIdx.x * TPB;
    const float* w  = dir ? w_b : w_f;
    const float* bb = dir ? b_b : b_f;
    float* pre = g_pre[dir];

    {   // gather TPB embedding rows into shared (8 threads per row)
        int i = tid >> 3, c = tid & 7;
        int f = feats[t0 + i];
        const float4* src = (const float4*)(emb + (size_t)f * EE);
        #pragma unroll
        for (int cc = 0; cc < 8; ++cc)
            ((float4*)xs[i])[c + cc * 8] = __ldg(src + c + cc * 8);
    }
    __syncthreads();

    for (int q = 0; q < 4; ++q) {
        const int row = q * 256 + tid;
        const float4* wp = (const float4*)(w + (size_t)row * EE);
        const float bv = __ldg(&bb[row]);
        float acc[TPB];
        #pragma unroll
        for (int i = 0; i < TPB; ++i) acc[i] = bv;
        for (int k4 = 0; k4 < 64; ++k4) {
            float4 wv = __ldg(wp + k4);
            #pragma unroll
            for (int i = 0; i < TPB; ++i) {
                float4 xv = *(const float4*)&xs[i][k4 * 4];
                acc[i] = fmaf(wv.x, xv.x, acc[i]);
                acc[i] = fmaf(wv.y, xv.y, acc[i]);
                acc[i] = fmaf(wv.z, xv.z, acc[i]);
                acc[i] = fmaf(wv.w, xv.w, acc[i]);
            }
        }
        #pragma unroll
        for (int i = 0; i < TPB; ++i)
            pre[(size_t)(t0 + i) * NG + row] = acc[i];
    }
}

// ---------------- persistent LSTM: 2 clusters of 8 CTAs ---------------------
// CTA owns 32 hidden units => 128 gate rows; 2 threads/row (256 threads).
// lane = unit_local*8 + gate*2 + half (all 4 gates of a unit in one warp).
// h broadcast via fine-grained st.async (DSMEM) + mbarrier, double buffered.
// Activations use MUFU rcp.approx (no precise-division sequences).
__global__ void __cluster_dims__(CS, 1, 1) __launch_bounds__(256, 1)
lstm_kernel(const float* __restrict__ whh_f, const float* __restrict__ whh_b)
{
    __shared__ __align__(16) float sh_h[2][HH];
    __shared__ ull smbar[2];

    const int tid = threadIdx.x;
    const int dir = blockIdx.x / CS;
    uint32_t rank;
    asm("mov.u32 %0, %%cluster_ctarank;" : "=r"(rank));

    const int w = tid >> 5, l = tid & 31;
    const int unit  = w * 4 + (l >> 3);            // 0..31 within CTA
    const int gate  = (l >> 1) & 3;                // 0..3 (i,f,g,o)
    const int half  = l & 1;                       // which 128-chunk of h
    const int unit_global = (int)rank * UPC + unit;   // 0..255
    const int row_global  = gate * HH + unit_global;  // 0..1023
    const bool is_gl = ((l & 7) == 0);             // publisher lane per unit

    // pack recurrent weights into f32x2 registers (128 floats / thread)
    const float* wrow = (dir ? whh_b : whh_f) + (size_t)row_global * HH + half * 128;
    ulonglong2 w2[32];
    #pragma unroll
    for (int v = 0; v < 32; ++v) {
        float4 f = __ldg((const float4*)wrow + v);
        w2[v].x = pack2(f.x, f.y);
        w2[v].y = pack2(f.z, f.w);
    }

    const uint32_t loc_h[2] = { smem_u32(&sh_h[0][unit_global]),
                                smem_u32(&sh_h[1][unit_global]) };
    const uint32_t loc_b[2] = { smem_u32(&smbar[0]), smem_u32(&smbar[1]) };
    uint32_t rem_h[2][CS], rem_b[2][CS];
    #pragma unroll
    for (int r = 0; r < CS; ++r) {
        rem_h[0][r] = mapa_rank(loc_h[0], r);
        rem_h[1][r] = mapa_rank(loc_h[1], r);
        rem_b[0][r] = mapa_rank(loc_b[0], r);
        rem_b[1][r] = mapa_rank(loc_b[1], r);
    }

    for (int i = tid; i < 2 * HH; i += 256) ((float*)sh_h)[i] = 0.f;
    if (tid == 0) { mbar_init(loc_b[0], 1); mbar_init(loc_b[1], 1); }
    __syncthreads();
    asm volatile("barrier.cluster.arrive.aligned;" ::: "memory");
    asm volatile("barrier.cluster.wait.aligned;" ::: "memory");

    const float* pre = g_pre[dir];
    float* hs = g_hs[dir];
    float c = 0.f;

    auto tmap = [&](int n) { return dir ? (TT - 1 - n) : n; };
    // prefetch pre with distance 2 (covers DRAM latency)
    float pre0 = 0.f, pre1 = 0.f;
    if (half == 0) {
        pre0 = __ldcg(&pre[(size_t)tmap(0) * NG + row_global]);
        pre1 = __ldcg(&pre[(size_t)tmap(1) * NG + row_global]);
    }

    for (int n = 0; n < TT; ++n) {
        const int tstep = tmap(n);
        if (n > 0) mbar_wait(loc_b[(n - 1) & 1], ((n - 1) >> 1) & 1);
        if (tid == 0) mbar_expect_tx(loc_b[n & 1], CS * UPC * 4);

        float pre2 = 0.f;
        if (half == 0 && n + 2 < TT)
            pre2 = __ldcg(&pre[(size_t)tmap(n + 2) * NG + row_global]);

        // ---- matvec slice: dot(w_row[half*128 .. +128), h_prev) -----------
        const ulonglong2* hp = (const ulonglong2*)&sh_h[(n + 1) & 1][half * 128];
        ull a0 = 0ull, a1 = 0ull, a2 = 0ull, a3 = 0ull;
        #pragma unroll
        for (int v = 0; v < 32; v += 2) {
            ulonglong2 h0 = hp[v], h1 = hp[v + 1];
            fma2(a0, w2[v].x, h0.x);     fma2(a1, w2[v].y, h0.y);
            fma2(a2, w2[v + 1].x, h1.x); fma2(a3, w2[v + 1].y, h1.y);
        }
        a0 = add2(add2(a0, a2), add2(a1, a3));
        float lo, hi; unpack2(lo, hi, a0);
        float dot = lo + hi;
        dot += __shfl_xor_sync(0xffffffffu, dot, 1);
        float val = dot + pre0;               // valid on even (half==0) lanes
        pre0 = pre1; pre1 = pre2;

        // ---- gather the 4 gates of this unit (all intra-warp) -------------
        const int base = l & 24;              // lane of (unit, gate0, half0)
        float gi = __shfl_sync(0xffffffffu, val, base);
        float gf = __shfl_sync(0xffffffffu, val, base + 2);
        float gg = __shfl_sync(0xffffffffu, val, base + 4);
        float go = __shfl_sync(0xffffffffu, val, base + 6);
        float iv = sigf(gi), fv = sigf(gf), ov = sigf(go);
        c = fv * c + iv * tanhf_fast(gg);     // replicated across unit lanes
        float h = ov * tanhf_fast(c);

        if (is_gl) {
            const int s = n & 1;
            const uint32_t hb = __float_as_uint(h);
            #pragma unroll
            for (int r = 0; r < CS; ++r) st_async_b32(rem_h[s][r], hb, rem_b[s][r]);
            hs[(size_t)tstep * HH + unit_global] = h;   // for emit (off path)
        }
    }

    // drain final publish, then cluster-exit barrier (peer stores in flight)
    mbar_wait(loc_b[(TT - 1) & 1], ((TT - 1) >> 1) & 1);
    asm volatile("barrier.cluster.arrive.aligned;" ::: "memory");
    asm volatile("barrier.cluster.wait.aligned;" ::: "memory");
}

// ---------------- emit: [hf|hb] @ W_out.T + b_out --------------------------
__global__ void __launch_bounds__(128) emit_kernel(
    const float* __restrict__ Wo, const float* __restrict__ bo)
{
    const int idx = blockIdx.x * blockDim.x + threadIdx.x;
    if (idx >= TT * LL) return;
    const int t = idx / LL;
    const int l = idx - t * LL;
    const float4* hf = (const float4*)&g_hs[0][(size_t)t * HH];
    const float4* hb = (const float4*)&g_hs[1][(size_t)t * HH];
    const float4* wf = (const float4*)&Wo[(size_t)l * 2 * HH];
    const float4* wb = wf + 64;
    float acc = __ldg(&bo[l]);
    #pragma unroll 8
    for (int k = 0; k < 64; ++k) {
        float4 h4 = __ldg(hf + k), w4 = __ldg(wf + k);
        acc = fmaf(h4.x, w4.x, acc); acc = fmaf(h4.y, w4.y, acc);
        acc = fmaf(h4.z, w4.z, acc); acc = fmaf(h4.w, w4.w, acc);
        float4 h5 = __ldg(hb + k), w5 = __ldg(wb + k);
        acc = fmaf(h5.x, w5.x, acc); acc = fmaf(h5.y, w5.y, acc);
        acc = fmaf(h5.z, w5.z, acc); acc = fmaf(h5.w, w5.w, acc);
    }
    g_emit[idx] = acc;
}

// ---------------- viterbi + backtrack (single warp, bp in shared) ----------
extern __shared__ unsigned char vit_sh[];
__global__ void viterbi_kernel(const float* __restrict__ trans,
                               float* __restrict__ out, int out_size)
{
    unsigned char* bp = vit_sh;                         // TT*LL bytes
    float* fvs = (float*)(vit_sh + (size_t)TT * LL);    // 2 x 32 floats

    const int l = threadIdx.x;
    float tr[LL];
    float tr_stop = 0.f;
    if (l < LL) {
        #pragma unroll
        for (int i = 0; i < LL; ++i) tr[i] = __ldg(&trans[i * LL + l]);
        tr_stop = __ldg(&trans[l * LL + STOPL]);
        fvs[l] = (l == STARTL) ? 0.f : NEGV;
    }
    __syncwarp();

    float e_nxt = (l < LL) ? __ldcg(&g_emit[l]) : 0.f;
    int cur = 0;
    for (int t = 0; t < TT; ++t) {
        const float e = e_nxt;
        if (l < LL && t + 1 < TT) e_nxt = __ldcg(&g_emit[(t + 1) * LL + l]);
        if (l < LL) {
            float sc[LL];
            #pragma unroll
            for (int i = 0; i < LL; ++i) sc[i] = fvs[cur * 32 + i] + tr[i];
            // tree max (depth 5)
            float m01 = fmaxf(sc[0], sc[1]),   m23 = fmaxf(sc[2], sc[3]);
            float m45 = fmaxf(sc[4], sc[5]),   m67 = fmaxf(sc[6], sc[7]);
            float m89 = fmaxf(sc[8], sc[9]),   mab = fmaxf(sc[10], sc[11]);
            float mcd = fmaxf(sc[12], sc[13]), mef = fmaxf(sc[14], sc[15]);
            float mgh = fmaxf(sc[16], sc[17]);
            float a = fmaxf(fmaxf(m01, m23), fmaxf(m45, m67));
            float b = fmaxf(fmaxf(m89, mab), fmaxf(mcd, mef));
            float m = fmaxf(fmaxf(a, b), mgh);
            unsigned mask = 0;
            #pragma unroll
            for (int i = 0; i < LL; ++i) mask |= (sc[i] == m) ? (1u << i) : 0u;
            int am = __ffs(mask) - 1;          // first index achieving max
            fvs[(cur ^ 1) * 32 + l] = m + e;
            bp[t * LL + l] = (unsigned char)am;
        }
        cur ^= 1;
        __syncwarp();
    }
    if (l < LL) fvs[cur * 32 + l] += tr_stop;   // terminal scores
    __syncwarp();

    if (l == 0) {
        float best = -3.4e38f; int bi = 0;
        #pragma unroll
        for (int i = 0; i < LL; ++i) {
            float v = fvs[cur * 32 + i];
            if (v > best) { best = v; bi = i; }
        }
        const int off = (out_size > TT) ? 1 : 0;
        if (off) out[0] = best;
        int tag = bi;
        for (int t = TT - 1; t >= 0; --t) {
            out[off + t] = (float)tag;
            if (t > 0) tag = (int)bp[t * LL + tag];
        }
    }
}

// ---------------- launch ----------------------------------------------------
extern "C" void kernel_launch(void* const* d_in, const int* in_sizes, int n_in,
                              void* d_out, int out_size)
{
    const int*   feats  = (const int*)d_in[0];
    const float* emb    = (const float*)d_in[1];
    const float* w_ih_f = (const float*)d_in[2];
    const float* w_hh_f = (const float*)d_in[3];
    const float* b_f    = (const float*)d_in[4];
    const float* w_ih_b = (const float*)d_in[5];
    const float* w_hh_b = (const float*)d_in[6];
    const float* b_b    = (const float*)d_in[7];
    const float* W_out  = (const float*)d_in[8];
    const float* b_out  = (const float*)d_in[9];
    const float* trans  = (const float*)d_in[10];
    float* out = (float*)d_out;

    const int vit_smem = TT * LL + 2 * 32 * (int)sizeof(float);  // ~74KB
    cudaFuncSetAttribute(viterbi_kernel,
                         cudaFuncAttributeMaxDynamicSharedMemorySize, vit_smem);

    pre_gemm_kernel<<<dim3(TT / TPB, 2), 256>>>(feats, emb, w_ih_f, b_f, w_ih_b, b_b);
    lstm_kernel<<<2 * CS, 256>>>(w_hh_f, w_hh_b);
    emit_kernel<<<(TT * LL + 127) / 128, 128>>>(W_out, b_out);
    viterbi_kernel<<<1, 32, vit_smem>>>(trans, out, out_size);
}